// round 4
// baseline (speedup 1.0000x reference)
#include <cuda_runtime.h>
#include <math.h>

#define H_IMG   256
#define NUM_V   512
#define NUM_F   1024
#define TPB     256

#define NTILES  256                  // (256/16)^2 tiles of 16x16 px
#define NCHUNK  16                   // power of two (wrap-safe counters)
#define CHUNK   64                   // faces per chunk

#define LOG_EPS (-13.815511f)        // log(1e-6) = log1p(-(1-1e-6))
#define HI_T    (0.03717f)           // dist>HI  => contribution == LOG_EPS exactly
#define LO_T    (-0.0448f)           // dist<LO  => |contribution| < 2.1e-9
#define TILE_R  (0.0830f)            // pixel-center half-diagonal of 16px tile
#define SKIP_C  (LO_T - TILE_R)
#define SAT_C   (HI_T + TILE_R)

// Device scratch (no allocations anywhere). Counters never reset: NCHUNK and
// NTILES are powers of two, so (old & (N-1)) == N-1 is wrap-safe across replays.
__device__ float    g_S[NCHUNK * H_IMG * H_IMG];
__device__ float    g_partial[NTILES];
__device__ unsigned g_tile_cnt[NTILES];
__device__ unsigned g_done;

__device__ __forceinline__ float face_dist(const float4 e0, const float4 e1,
                                           const float4 e2, float qx, float qy)
{
    float d0 = fmaf(e0.x, qx, fmaf(e0.y, qy, e0.z));
    float d1 = fmaf(e1.x, qx, fmaf(e1.y, qy, e1.z));
    float d2 = fmaf(e2.x, qx, fmaf(e2.y, qy, e2.z));
    float dmin = fminf(fminf(d0, d1), d2);
    float dmax = fmaxf(fmaxf(d0, d1), d2);
    return fmaxf(dmin, -dmax);
}

// ---------------------------------------------------------------------------
// Single fused kernel. Grid (NTILES, NCHUNK).
//   Phase A: per-block projection of its 64-face chunk.
//   Phase B: Lipschitz tile classification (ballot compaction).
//   Phase C: per-pixel band loop -> g_S.
//   Phase D: 16th block per tile combines chunks (L2-hot), SSE -> g_partial.
//   Phase E: 256th tile-finisher does fixed-order final reduce + penalty.
// All FP sum orders fixed => deterministic. No spin-waits => no deadlock.
// ---------------------------------------------------------------------------
__global__ void __launch_bounds__(TPB)
fused_kernel(const float* __restrict__ verts,
             const int*   __restrict__ faces,
             const float* __restrict__ cam,
             const float* __restrict__ img,
             float*       __restrict__ out)
{
    __shared__ float4 sf[CHUNK * 3];   // 3 KB
    __shared__ int    slist[CHUNK];
    __shared__ int    wcnt[2];
    __shared__ int    wsat[2];
    __shared__ float  red[8];
    __shared__ unsigned elect;

    const int tid  = threadIdx.x;
    const int tile = blockIdx.x;
    const int c    = blockIdx.y;

    // ---- Phase A: project this chunk's 64 faces (threads 0..63) ----
    if (tid < CHUNK) {
        const int f = c * CHUNK + tid;

        float ex = __ldg(&cam[0]), ey = __ldg(&cam[1]), ez = __ldg(&cam[2]);

        float nl = sqrtf(ex*ex + ey*ey + ez*ez) + 1e-8f;
        float zx = -ex/nl, zy = -ey/nl, zz = -ez/nl;
        float cl = sqrtf(zz*zz + zx*zx) + 1e-8f;
        float xax = zz/cl, xay = 0.0f, xaz = -zx/cl;   // normalize(cross(up,z))
        float yx = zy*xaz - zz*xay;
        float yy = zz*xax - zx*xaz;
        float yz = zx*xay - zy*xax;
        float yl = sqrtf(yx*yx + yy*yy + yz*yz) + 1e-8f;
        yx /= yl; yy /= yl; yz /= yl;

        const float t = 0.57735026918962576f;  // tan(30deg)

        float sx[3], sy[3];
        bool valid = true;
        #pragma unroll
        for (int k = 0; k < 3; k++) {
            int vi = __ldg(&faces[f*3 + k]);
            float px = __ldg(&verts[vi*3 + 0]) - ex;
            float py = __ldg(&verts[vi*3 + 1]) - ey;
            float pz = __ldg(&verts[vi*3 + 2]) - ez;
            float X = px*xax + py*xay + pz*xaz;
            float Y = px*yx  + py*yy  + pz*yz;
            float Z = px*zx  + py*zy  + pz*zz;
            valid = valid && (Z > 0.001f);
            float den = Z*t + 1e-8f;
            sx[k] = X / den;
            sy[k] = Y / den;
        }

        #pragma unroll
        for (int k = 0; k < 3; k++) {
            int a = k;
            int b = (k == 2) ? 0 : (k + 1);
            float eex = sx[b] - sx[a];
            float eey = sy[b] - sy[a];
            float il  = 1.0f / (sqrtf(eex*eex + eey*eey) + 1e-8f);
            float A = -eey * il;
            float B =  eex * il;
            float C = (eey * sx[a] - eex * sy[a]) * il;
            if (!valid) {           // sentinel: dist=-1e30 -> always skipped
                A = 0.0f; B = 0.0f;
                C = (k == 2) ? 1e30f : -1e30f;
            }
            sf[tid*3 + k] = make_float4(A, B, C, 0.0f);
        }
    }
    __syncthreads();

    // ---- Phase B: tile classification (dist is 1-Lipschitz in q) ----
    const int tx = tile & 15, ty = tile >> 4;
    const float cx =  ((tx * 16 + 8.0f) / 128.0f) - 1.0f;
    const float cy = -(((ty * 16 + 8.0f) / 128.0f) - 1.0f);

    const int w = tid >> 5, lane = tid & 31;
    if (w < 2) {
        int fi = w * 32 + lane;
        float dc = face_dist(sf[3*fi], sf[3*fi+1], sf[3*fi+2], cx, cy);
        bool sat  = (dc > SAT_C);
        bool band = (dc > SKIP_C) && !sat;
        unsigned mb = __ballot_sync(0xffffffffu, band);
        unsigned ms = __ballot_sync(0xffffffffu, sat);
        if (band) {
            int pos = __popc(mb & ((1u << lane) - 1u));
            slist[w * 32 + pos] = fi;
        }
        if (lane == 0) {
            wcnt[w] = __popc(mb);
            wsat[w] = __popc(ms);
        }
    }
    __syncthreads();

    const int sat_total = wsat[0] + wsat[1];

    // ---- Phase C: per-pixel band loop ----
    const int col = tx * 16 + (tid & 15);
    const int row = ty * 16 + (tid >> 4);
    const int pix = row * H_IMG + col;
    const float qx =  ((col + 0.5f) / 128.0f) - 1.0f;
    const float qy = -(((row + 0.5f) / 128.0f) - 1.0f);

    float S   = 0.0f;
    int   cnt = sat_total;

    #pragma unroll 1
    for (int ww = 0; ww < 2; ww++) {
        const int n = wcnt[ww];
        for (int j = 0; j < n; j++) {
            int fi = slist[ww * 32 + j];
            float dist = face_dist(sf[3*fi], sf[3*fi+1], sf[3*fi+2], qx, qy);
            if (dist > HI_T) {
                cnt++;
            } else if (dist > LO_T) {
                float x  = dist * fabsf(dist) * 1e4f;
                float ax = fabsf(x);
                float sp = ax + log1pf(__expf(-ax));     // softplus(|x|)
                float cc = (x > 0.0f) ? -sp : (ax - sp); // -softplus(x)
                S += fmaxf(cc, LOG_EPS);
            }
        }
    }

    S += (float)cnt * LOG_EPS;
    g_S[c * (H_IMG * H_IMG) + pix] = S;

    // ---- Phase D election: 16th arrival for this tile combines it ----
    __threadfence();
    __syncthreads();
    if (tid == 0) elect = atomicAdd(&g_tile_cnt[tile], 1u);
    __syncthreads();
    if ((elect & (NCHUNK - 1)) != (NCHUNK - 1)) return;

    float Ssum = 0.0f;
    #pragma unroll
    for (int cc = 0; cc < NCHUNK; cc++)                   // fixed order
        Ssum += __ldcg(&g_S[cc * (H_IMG * H_IMG) + pix]); // L1-bypass (coherent)

    float alpha = 1.0f - expf(Ssum);
    float r = __ldg(&img[pix]) - alpha;
    float v = r * r;

    #pragma unroll
    for (int o = 16; o > 0; o >>= 1)
        v += __shfl_down_sync(0xffffffffu, v, o);
    if (lane == 0) red[w] = v;
    __syncthreads();

    if (tid == 0) {
        float bs = 0.0f;
        #pragma unroll
        for (int i = 0; i < 8; i++) bs += red[i];         // fixed order
        g_partial[tile] = bs;
        __threadfence();
        elect = atomicAdd(&g_done, 1u);
    }
    __syncthreads();

    // ---- Phase E: 256th tile-finisher does the final reduce ----
    if ((elect & (NTILES - 1)) != (NTILES - 1)) return;

    __shared__ float fred[TPB];
    fred[tid] = __ldcg(&g_partial[tid]);                  // NTILES == TPB
    __syncthreads();
    #pragma unroll
    for (int o = TPB / 2; o > 0; o >>= 1) {               // fixed-order tree
        if (tid < o) fred[tid] += fred[tid + o];
        __syncthreads();
    }
    if (tid == 0) {
        float ex = __ldg(&cam[0]), ey = __ldg(&cam[1]), ez = __ldg(&cam[2]);
        float d = sqrtf(ex*ex + ey*ey + ez*ez);
        float pen = fmaxf(0.0f, 6.0f - d);
        out[0] = fred[0] * (1.0f + pen);
    }
}

// ---------------------------------------------------------------------------
extern "C" void kernel_launch(void* const* d_in, const int* in_sizes, int n_in,
                              void* d_out, int out_size)
{
    const float* verts = nullptr;
    const int*   faces = nullptr;
    const float* img   = nullptr;
    const float* cam   = nullptr;

    for (int i = 0; i < n_in; i++) {
        switch (in_sizes[i]) {
            case NUM_V * 3:      verts = (const float*)d_in[i]; break;
            case NUM_F * 3:      faces = (const int*)  d_in[i]; break;
            case H_IMG * H_IMG:  img   = (const float*)d_in[i]; break;
            case 3:              cam   = (const float*)d_in[i]; break;
            default: break;
        }
    }

    dim3 grid(NTILES, NCHUNK);
    fused_kernel<<<grid, TPB>>>(verts, faces, cam, img, (float*)d_out);
}